// round 14
// baseline (speedup 1.0000x reference)
#include <cuda_runtime.h>
#include <cuda_fp16.h>
#include <cstdint>
#include <math.h>

// Problem constants
#define BB 128
#define HH 16
#define WW 48
#define DD 512
#define UU 512
#define HW (HH*WW)          // 768
#define MM (BB*HW)          // 98304

// ---------------------------------------------------------------------------
// Device globals (scratch; no allocation allowed)
// ---------------------------------------------------------------------------
__device__ float  g_dec_proj[BB*UU];          // dec @ W2 + b1 + b2
__device__ float  g_part[4*MM];               // partial scores per N-quarter
__device__ __half g_W1T[UU*DD];               // W1^T fp16 [u][k]
__device__ __half g_enc16[(size_t)MM*DD];     // enc fp16 [m][k]

// ---------------------------------------------------------------------------
// Helpers
// ---------------------------------------------------------------------------
__device__ __forceinline__ uint32_t smem_u32(const void* p) {
    uint32_t a;
    asm("{ .reg .u64 t; cvta.to.shared.u64 t, %1; cvt.u32.u64 %0, t; }"
        : "=r"(a) : "l"(p));
    return a;
}

__device__ __forceinline__ void cp16(uint32_t s, const void* g) {
    asm volatile("cp.async.cg.shared.global [%0], [%1], 16;"
                 :: "r"(s), "l"(g) : "memory");
}
__device__ __forceinline__ void cp_commit() {
    asm volatile("cp.async.commit_group;" ::: "memory");
}
#define CP_WAIT(n) asm volatile("cp.async.wait_group %0;" :: "n"(n) : "memory")

__device__ __forceinline__ void ldsm4(uint32_t* r, uint32_t addr) {
    asm volatile("ldmatrix.sync.aligned.m8n8.x4.shared.b16 {%0,%1,%2,%3}, [%4];"
                 : "=r"(r[0]), "=r"(r[1]), "=r"(r[2]), "=r"(r[3]) : "r"(addr));
}

__device__ __forceinline__ void mma_f16(float* c, const uint32_t* a,
                                        uint32_t b0, uint32_t b1) {
    asm volatile("mma.sync.aligned.m16n8k16.row.col.f32.f16.f16.f32 "
                 "{%0,%1,%2,%3}, {%4,%5,%6,%7}, {%8,%9}, {%0,%1,%2,%3};"
                 : "+f"(c[0]), "+f"(c[1]), "+f"(c[2]), "+f"(c[3])
                 : "r"(a[0]), "r"(a[1]), "r"(a[2]), "r"(a[3]),
                   "r"(b0), "r"(b1));
}

// fast tanh: (e^{2x}-1)/(e^{2x}+1), clamped so e^{2x} never overflows
__device__ __forceinline__ float fast_tanh(float x) {
    x = fminf(10.f, fmaxf(-10.f, x));
    float t = __expf(2.f * x);
    return __fdividef(t - 1.f, t + 1.f);
}

// ---------------------------------------------------------------------------
// K0: merged prep — latency-bound / tiny blocks FIRST, enc wave LAST.
//   Blocks [0, 32):            zero d_out ctx region (graph-replay safe)
//   Blocks [32, 160):          dec_proj, 1 batch per block
//   Blocks [160, 416):         W1 -> transposed fp16 (256 float4s each)
//   Blocks [416, 416+12288):   enc fp32 -> fp16, 4 float4s per thread (MLP 4)
// ---------------------------------------------------------------------------
#define Z_BLKS    32
#define DP_BLKS   128
#define W1_BLKS   256
#define ENC_BLKS  12288      // MM*DD/4 float4s / (256 threads * 4 each)

__global__ __launch_bounds__(256) void prep_all_kernel(
    const float* __restrict__ enc, const float* __restrict__ W1,
    const float* __restrict__ dec, const float* __restrict__ W2,
    const float* __restrict__ b1, const float* __restrict__ b2,
    float* __restrict__ ctx_out) {
    const int bx = blockIdx.x;
    const int tid = threadIdx.x;

    if (bx >= Z_BLKS + DP_BLKS + W1_BLKS) {
        // enc fp32 -> fp16: 4 independent float4 loads in flight per thread
        size_t base = (size_t)(bx - Z_BLKS - DP_BLKS - W1_BLKS) * 1024 + tid;
        float4 v0 = __ldcs((const float4*)enc + base);
        float4 v1 = __ldcs((const float4*)enc + base + 256);
        float4 v2 = __ldcs((const float4*)enc + base + 512);
        float4 v3 = __ldcs((const float4*)enc + base + 768);
        __half2 a0 = __floats2half2_rn(v0.x, v0.y), b0h = __floats2half2_rn(v0.z, v0.w);
        __half2 a1 = __floats2half2_rn(v1.x, v1.y), b1h = __floats2half2_rn(v1.z, v1.w);
        __half2 a2 = __floats2half2_rn(v2.x, v2.y), b2h = __floats2half2_rn(v2.z, v2.w);
        __half2 a3 = __floats2half2_rn(v3.x, v3.y), b3h = __floats2half2_rn(v3.z, v3.w);
        ((uint2*)g_enc16)[base]       = make_uint2(reinterpret_cast<uint32_t&>(a0),
                                                   reinterpret_cast<uint32_t&>(b0h));
        ((uint2*)g_enc16)[base + 256] = make_uint2(reinterpret_cast<uint32_t&>(a1),
                                                   reinterpret_cast<uint32_t&>(b1h));
        ((uint2*)g_enc16)[base + 512] = make_uint2(reinterpret_cast<uint32_t&>(a2),
                                                   reinterpret_cast<uint32_t&>(b2h));
        ((uint2*)g_enc16)[base + 768] = make_uint2(reinterpret_cast<uint32_t&>(a3),
                                                   reinterpret_cast<uint32_t&>(b3h));
    } else if (bx >= Z_BLKS + DP_BLKS) {
        // W1[k][u] -> g_W1T[u][k] fp16
        int i4 = (bx - Z_BLKS - DP_BLKS) * 256 + tid;  // 0..65535
        int base = i4 * 4;
        int k = base >> 9, u = base & 511;
        float4 v = *(const float4*)(W1 + base);
        g_W1T[(u+0)*DD + k] = __float2half_rn(v.x);
        g_W1T[(u+1)*DD + k] = __float2half_rn(v.y);
        g_W1T[(u+2)*DD + k] = __float2half_rn(v.z);
        g_W1T[(u+3)*DD + k] = __float2half_rn(v.w);
    } else if (bx >= Z_BLKS) {
        // dec_proj: one batch per block; thread owns u=tid and u=tid+256
        __shared__ float s_dec[DD];
        int b0 = bx - Z_BLKS;
        for (int i = tid; i < DD; i += 256) s_dec[i] = dec[b0*DD + i];
        __syncthreads();
        int u0 = tid, u1 = tid + 256;
        float a0 = b1[u0] + b2[u0];
        float a1 = b1[u1] + b2[u1];
        #pragma unroll 4
        for (int d = 0; d < DD; d++) {
            float dv = s_dec[d];
            a0 += dv * W2[(size_t)d*UU + u0];
            a1 += dv * W2[(size_t)d*UU + u1];
        }
        g_dec_proj[b0*UU + u0] = a0;
        g_dec_proj[b0*UU + u1] = a1;
    } else {
        // zero the ctx region of d_out (atomic accumulation target)
        int i = bx * 256 + tid;            // 0..8191, 2 float4s each
        float4 z = {0.f, 0.f, 0.f, 0.f};
        ((float4*)ctx_out)[i] = z;
        ((float4*)ctx_out)[i + 8192] = z;
    }
}

// ---------------------------------------------------------------------------
// K2: fp16 score GEMM, 2 CTAs/SM.  CTA tile 128(m) x 128(n), 256 threads,
//   8 warps (4m x 2n, warp tile 32x64). K-chunk 64.
//   Stage = A 16K + W 16K = 32KB; 3 stages = 96KB; 1 sync/chunk.
//   grid = 3072: mtile = bx>>2, nq = bx&3 (n-fast for A L2 reuse).
// ---------------------------------------------------------------------------
#define STAGE 32768
#define SMEM_DYN (3*STAGE)   // 96KB

__global__ __launch_bounds__(256, 2) void score_kernel(const float* __restrict__ Vw) {
    extern __shared__ char dsm[];
    __shared__ float dp_s[128];
    __shared__ float vw_s[128];
    __shared__ float s_red[2][128];

    const uint32_t sb = smem_u32(dsm);
    const int tid  = threadIdx.x;
    const int wid  = tid >> 5;
    const int lane = tid & 31;
    const int mtile = blockIdx.x >> 2;
    const int nq    = blockIdx.x & 3;
    const int row0  = mtile * 128;
    const int b     = mtile / 6;          // 6 m-tiles per batch
    const int m0 = (wid >> 1) * 32;       // warp m-offset (0..96)
    const int n0 = (wid & 1) * 64;        // warp n-offset (0/64)
    const int rl = lane >> 2;             // fragment row group 0..7
    const int qt = lane & 3;              // fragment col group

    // ldmatrix lane addressing constants (validated rounds 4-13)
    const int sub = lane >> 3, i8 = lane & 7;
    const uint32_t x8   = (uint32_t)i8;
    const uint32_t aRow = (uint32_t)(m0 + ((sub & 1) << 3) + i8) * 128;
    const uint32_t aCS  = (uint32_t)(sub >> 1);
    const uint32_t bRow = (uint32_t)(n0 + ((sub >> 1) << 3) + i8) * 128;
    const uint32_t bCS  = (uint32_t)(sub & 1);

    uint32_t aChunk[4], bChunk[4];
    #pragma unroll
    for (int ks = 0; ks < 4; ks++) {
        aChunk[ks] = (((uint32_t)(2*ks) + aCS) ^ x8) << 4;
        bChunk[ks] = (((uint32_t)(2*ks) + bCS) ^ x8) << 4;
    }

    if (tid < 128) {
        dp_s[tid] = g_dec_proj[b*UU + nq*128 + tid];
        vw_s[tid] = Vw[nq*128 + tid];
    }

    float acc[2][8][4];
    #pragma unroll
    for (int mi = 0; mi < 2; mi++)
        #pragma unroll
        for (int j = 0; j < 8; j++)
            #pragma unroll
            for (int c = 0; c < 4; c++) acc[mi][j][c] = 0.f;

    const __half* __restrict__ Ap = g_enc16 + (size_t)row0*DD;
    const __half* __restrict__ Wp = g_W1T + (size_t)(nq*128)*DD;

    // ---- producer: one K=64 chunk (A + W), all cp.async ----
    auto produce = [&](int kt) {
        const uint32_t as = sb + (uint32_t)(kt % 3)*STAGE;
        const uint32_t ws = as + 16384;
        const int kk = kt * 64;
        #pragma unroll
        for (int i = 0; i < 4; i++) {          // A: 1024 x 16B
            int id = tid + i*256;
            int r = id >> 3, j = id & 7;
            uint32_t off = (uint32_t)r*128 + (uint32_t)((j ^ (r & 7)) << 4);
            cp16(as + off, Ap + (size_t)r*DD + kk + j*8);
        }
        #pragma unroll
        for (int i = 0; i < 4; i++) {          // W: 1024 x 16B
            int id = tid + i*256;
            int r = id >> 3, j = id & 7;
            uint32_t off = (uint32_t)r*128 + (uint32_t)((j ^ (r & 7)) << 4);
            cp16(ws + off, Wp + (size_t)r*DD + kk + j*8);
        }
        cp_commit();
    };

    // ---- prologue: fill 2 of 3 stages ----
    produce(0);
    produce(1);

    // ---- mainloop: 8 chunks, ONE sync per chunk ----
    #pragma unroll 1
    for (int kt = 0; kt < 8; kt++) {
        if (kt < 7) { CP_WAIT(1); } else { CP_WAIT(0); }
        __syncthreads();                   // chunk kt ready; stage kt-1 drained
        if (kt + 2 < 8) produce(kt + 2);   // overwrites stage consumed at kt-1

        const uint32_t st  = sb + (uint32_t)(kt % 3)*STAGE;
        const uint32_t stW = st + 16384u;
        #pragma unroll
        for (int ks = 0; ks < 4; ks++) {
            uint32_t bq[4][4];
            #pragma unroll
            for (int jp = 0; jp < 4; jp++)
                ldsm4(bq[jp], stW + bRow + (uint32_t)jp*2048 + bChunk[ks]);
            uint32_t a0[4], a1[4];
            ldsm4(a0, st + aRow + aChunk[ks]);
            ldsm4(a1, st + aRow + 2048 + aChunk[ks]);
            #pragma unroll
            for (int jp = 0; jp < 4; jp++) {
                mma_f16(acc[0][2*jp],   a0, bq[jp][0], bq[jp][1]);
                mma_f16(acc[1][2*jp],   a1, bq[jp][0], bq[jp][1]);
                mma_f16(acc[0][2*jp+1], a0, bq[jp][2], bq[jp][3]);
                mma_f16(acc[1][2*jp+1], a1, bq[jp][2], bq[jp][3]);
            }
        }
    }

    // ---- epilogue: fast tanh + V-dot ----
    float p[4] = {0.f, 0.f, 0.f, 0.f};
    #pragma unroll
    for (int mi = 0; mi < 2; mi++)
        #pragma unroll
        for (int j = 0; j < 8; j++)
            #pragma unroll
            for (int cc = 0; cc < 4; cc++) {
                int u = n0 + j*8 + qt*2 + (cc & 1);
                int h = cc >> 1;
                p[mi*2 + h] += fast_tanh(acc[mi][j][cc] + dp_s[u]) * vw_s[u];
            }
    #pragma unroll
    for (int i = 0; i < 4; i++) {
        p[i] += __shfl_xor_sync(0xFFFFFFFF, p[i], 1);
        p[i] += __shfl_xor_sync(0xFFFFFFFF, p[i], 2);
    }
    if (qt == 0) {
        #pragma unroll
        for (int mi = 0; mi < 2; mi++)
            #pragma unroll
            for (int h = 0; h < 2; h++)
                s_red[wid & 1][m0 + mi*16 + h*8 + rl] = p[mi*2 + h];
    }
    __syncthreads();
    if (tid < 128)
        g_part[nq*MM + row0 + tid] = s_red[0][tid] + s_red[1][tid];
}

// ---------------------------------------------------------------------------
// K4: fused softmax + context (atomic accumulate). grid(128,8), 128 threads.
//   Block (b,q): recomputes softmax over H for batch b (from g_part, L2-hot),
//   writes attn rows h=2q,2q+1 (exactly once across q), then atomically adds
//   its 96-row context partial into ctx_out (zeroed by prep_all).
// ---------------------------------------------------------------------------
__global__ __launch_bounds__(128) void ctx_sm_kernel(float* __restrict__ attn,
                                                     float* __restrict__ ctx_out) {
    __shared__ float sc[HW];
    __shared__ float s_a[96];
    int b = blockIdx.x, q = blockIdx.y;
    int t = threadIdx.x;
    int base = q * 96;

    // load + sum 4 score planes for the whole batch
    #pragma unroll
    for (int i = t; i < HW; i += 128) {
        const float* p0 = g_part + b*HW + i;
        sc[i] = (p0[0] + p0[MM]) + (p0[2*MM] + p0[3*MM]);
    }
    __syncthreads();

    // softmax over h per w; write attn rows h0=2q, h0+1
    if (t < WW) {
        int w = t;
        int h0 = 2*q;
        float mx = -1e30f;
        #pragma unroll
        for (int h = 0; h < HH; h++) mx = fmaxf(mx, sc[h*WW + w]);
        float sum = 0.f, e0 = 0.f, e1 = 0.f;
        #pragma unroll
        for (int h = 0; h < HH; h++) {
            float e = __expf(sc[h*WW + w] - mx);
            sum += e;
            if (h == h0)     e0 = e;
            if (h == h0 + 1) e1 = e;
        }
        float inv = 1.0f / sum;
        float a0 = e0 * inv, a1 = e1 * inv;
        attn[b*HW + h0*WW + w] = a0;
        attn[b*HW + (h0+1)*WW + w] = a1;
        s_a[w] = a0;
        s_a[WW + w] = a1;
    }
    __syncthreads();

    // context partial over 96 rows
    const uint2* __restrict__ e =
        (const uint2*)(g_enc16 + ((size_t)b*HW + base)*DD) + t;   // 4 halves/thread
    float4 a0 = {0,0,0,0}, a1 = a0, a2 = a0, a3 = a0;
    #pragma unroll 4
    for (int i = 0; i < 96; i += 4) {
        float w0 = s_a[i], w1 = s_a[i+1], w2 = s_a[i+2], w3 = s_a[i+3];
        uint2 v0 = e[(size_t)(i+0)*128];
        uint2 v1 = e[(size_t)(i+1)*128];
        uint2 v2 = e[(size_t)(i+2)*128];
        uint2 v3 = e[(size_t)(i+3)*128];
        float2 f0a = __half22float2(reinterpret_cast<__half2&>(v0.x));
        float2 f0b = __half22float2(reinterpret_cast<__half2&>(v0.y));
        float2 f1a = __half22float2(reinterpret_cast<__half2&>(v1.x));
        float2 f1b = __half22float2(reinterpret_cast<__half2&>(v1.y));
        float2 f2a = __half22float2(reinterpret_cast<__half2&>(v2.x));
        float2 f2b = __half22float2(reinterpret_cast<__half2&>(v2.y));
        float2 f3a = __half22float2(reinterpret_cast<__half2&>(v3.x));
        float2 f3b = __half22float2(reinterpret_cast<__half2&>(v3.y));
        a0.x += w0*f0a.x; a0.y += w0*f0a.y; a0.z += w0*f0b.x; a0.w += w0*f0b.y;
        a1.x += w1*f1a.x; a1.y += w1*f1a.y; a1.z += w1*f1b.x; a1.w += w1*f1b.y;
        a2.x += w2*f2a.x; a2.y += w2*f2a.y; a2.z += w2*f2b.x; a2.w += w2*f2b.y;
        a3.x += w3*f3a.x; a3.y += w3*f3a.y; a3.z += w3*f3b.x; a3.w += w3*f3b.y;
    }
    float* dst = ctx_out + (size_t)b*DD + t*4;
    atomicAdd(dst + 0, (a0.x + a1.x) + (a2.x + a3.x));
    atomicAdd(dst + 1, (a0.y + a1.y) + (a2.y + a3.y));
    atomicAdd(dst + 2, (a0.z + a1.z) + (a2.z + a3.z));
    atomicAdd(dst + 3, (a0.w + a1.w) + (a2.w + a3.w));
}

// ---------------------------------------------------------------------------
extern "C" void kernel_launch(void* const* d_in, const int* in_sizes, int n_in,
                              void* d_out, int out_size) {
    const float* dec  = (const float*)d_in[0];   // (128, 512)
    const float* enc  = (const float*)d_in[1];   // (128, 16, 48, 512)
    const float* W1w  = (const float*)d_in[2];   // (512, 512)
    const float* W1b  = (const float*)d_in[3];
    const float* W2w  = (const float*)d_in[4];
    const float* W2b  = (const float*)d_in[5];
    const float* Vw   = (const float*)d_in[6];   // (512, 1)
    // V_b unused: cancels in softmax.

    float* ctx_out  = (float*)d_out;             // (128, 512)
    float* attn_out = (float*)d_out + BB*DD;     // (128, 16, 48, 1)

    static bool attr_set = false;
    if (!attr_set) {
        cudaFuncSetAttribute(score_kernel,
                             cudaFuncAttributeMaxDynamicSharedMemorySize, SMEM_DYN);
        attr_set = true;
    }

    prep_all_kernel<<<Z_BLKS + DP_BLKS + W1_BLKS + ENC_BLKS, 256>>>(
        enc, W1w, dec, W2w, W1b, W2b, ctx_out);
    score_kernel<<<(MM/128)*4, 256, SMEM_DYN>>>(Vw);
    ctx_sm_kernel<<<dim3(BB, 8), 128>>>(attn_out, ctx_out);
}

// round 15
// speedup vs baseline: 1.0188x; 1.0188x over previous
#include <cuda_runtime.h>
#include <cuda_fp16.h>
#include <cstdint>
#include <math.h>

// Problem constants
#define BB 128
#define HH 16
#define WW 48
#define DD 512
#define UU 512
#define HW (HH*WW)          // 768
#define MM (BB*HW)          // 98304
#define TILES 3072          // (MM/128) m-tiles * 4 n-quarters
#define SGRID 296           // persistent score CTAs (<= 2 per SM)

// ---------------------------------------------------------------------------
// Device globals (scratch; no allocation allowed)
// ---------------------------------------------------------------------------
__device__ float  g_dec_proj[BB*UU];          // dec @ W2 + b1 + b2
__device__ float  g_part[4*MM];               // partial scores per N-quarter
__device__ __half g_W1T[UU*DD];               // W1^T fp16 [u][k]
__device__ __half g_enc16[(size_t)MM*DD];     // enc fp16 [m][k]

// ---------------------------------------------------------------------------
// Helpers
// ---------------------------------------------------------------------------
__device__ __forceinline__ uint32_t smem_u32(const void* p) {
    uint32_t a;
    asm("{ .reg .u64 t; cvta.to.shared.u64 t, %1; cvt.u32.u64 %0, t; }"
        : "=r"(a) : "l"(p));
    return a;
}

__device__ __forceinline__ void cp16(uint32_t s, const void* g) {
    asm volatile("cp.async.cg.shared.global [%0], [%1], 16;"
                 :: "r"(s), "l"(g) : "memory");
}
__device__ __forceinline__ void cp_commit() {
    asm volatile("cp.async.commit_group;" ::: "memory");
}
#define CP_WAIT(n) asm volatile("cp.async.wait_group %0;" :: "n"(n) : "memory")

__device__ __forceinline__ void ldsm4(uint32_t* r, uint32_t addr) {
    asm volatile("ldmatrix.sync.aligned.m8n8.x4.shared.b16 {%0,%1,%2,%3}, [%4];"
                 : "=r"(r[0]), "=r"(r[1]), "=r"(r[2]), "=r"(r[3]) : "r"(addr));
}

__device__ __forceinline__ void mma_f16(float* c, const uint32_t* a,
                                        uint32_t b0, uint32_t b1) {
    asm volatile("mma.sync.aligned.m16n8k16.row.col.f32.f16.f16.f32 "
                 "{%0,%1,%2,%3}, {%4,%5,%6,%7}, {%8,%9}, {%0,%1,%2,%3};"
                 : "+f"(c[0]), "+f"(c[1]), "+f"(c[2]), "+f"(c[3])
                 : "r"(a[0]), "r"(a[1]), "r"(a[2]), "r"(a[3]),
                   "r"(b0), "r"(b1));
}

// fast tanh: (e^{2x}-1)/(e^{2x}+1), clamped so e^{2x} never overflows
__device__ __forceinline__ float fast_tanh(float x) {
    x = fminf(10.f, fmaxf(-10.f, x));
    float t = __expf(2.f * x);
    return __fdividef(t - 1.f, t + 1.f);
}

// ---------------------------------------------------------------------------
// K0: merged prep (round-13 validated form) — tiny blocks FIRST, enc LAST.
//   Blocks [0, 32):            zero d_out ctx region (graph-replay safe)
//   Blocks [32, 160):          dec_proj, 1 batch per block
//   Blocks [160, 416):         W1 -> transposed fp16 (256 float4s each)
//   Blocks [416, 416+49152):   enc fp32 -> fp16 (1 float4 per thread)
// ---------------------------------------------------------------------------
#define Z_BLKS    32
#define DP_BLKS   128
#define W1_BLKS   256
#define ENC_BLKS  49152      // MM*DD/4 float4s / 256 threads

__global__ __launch_bounds__(256) void prep_all_kernel(
    const float* __restrict__ enc, const float* __restrict__ W1,
    const float* __restrict__ dec, const float* __restrict__ W2,
    const float* __restrict__ b1, const float* __restrict__ b2,
    float* __restrict__ ctx_out) {
    const int bx = blockIdx.x;
    const int tid = threadIdx.x;

    if (bx >= Z_BLKS + DP_BLKS + W1_BLKS) {
        // enc fp32 -> fp16  (streaming loads: fp32 never reused)
        size_t i4 = (size_t)(bx - Z_BLKS - DP_BLKS - W1_BLKS) * 256 + tid;
        float4 v = __ldcs((const float4*)enc + i4);
        __half2 h01 = __floats2half2_rn(v.x, v.y);
        __half2 h23 = __floats2half2_rn(v.z, v.w);
        ((uint2*)g_enc16)[i4] = make_uint2(reinterpret_cast<uint32_t&>(h01),
                                           reinterpret_cast<uint32_t&>(h23));
    } else if (bx >= Z_BLKS + DP_BLKS) {
        // W1[k][u] -> g_W1T[u][k] fp16
        int i4 = (bx - Z_BLKS - DP_BLKS) * 256 + tid;  // 0..65535
        int base = i4 * 4;
        int k = base >> 9, u = base & 511;
        float4 v = *(const float4*)(W1 + base);
        g_W1T[(u+0)*DD + k] = __float2half_rn(v.x);
        g_W1T[(u+1)*DD + k] = __float2half_rn(v.y);
        g_W1T[(u+2)*DD + k] = __float2half_rn(v.z);
        g_W1T[(u+3)*DD + k] = __float2half_rn(v.w);
    } else if (bx >= Z_BLKS) {
        // dec_proj: one batch per block; thread owns u=tid and u=tid+256
        __shared__ float s_dec[DD];
        int b0 = bx - Z_BLKS;
        for (int i = tid; i < DD; i += 256) s_dec[i] = dec[b0*DD + i];
        __syncthreads();
        int u0 = tid, u1 = tid + 256;
        float a0 = b1[u0] + b2[u0];
        float a1 = b1[u1] + b2[u1];
        #pragma unroll 4
        for (int d = 0; d < DD; d++) {
            float dv = s_dec[d];
            a0 += dv * W2[(size_t)d*UU + u0];
            a1 += dv * W2[(size_t)d*UU + u1];
        }
        g_dec_proj[b0*UU + u0] = a0;
        g_dec_proj[b0*UU + u1] = a1;
    } else {
        // zero the ctx region of d_out (atomic accumulation target)
        int i = bx * 256 + tid;            // 0..8191, 2 float4s each
        float4 z = {0.f, 0.f, 0.f, 0.f};
        ((float4*)ctx_out)[i] = z;
        ((float4*)ctx_out)[i + 8192] = z;
    }
}

// ---------------------------------------------------------------------------
// K2: PERSISTENT fp16 score GEMM, 2 CTAs/SM, 296 CTAs, ~10 tiles each.
//   CTA tile 128(m) x 128(n), 256 threads, 8 warps (4m x 2n).
//   Continuous 3-stage cp.async ring across tile boundaries; 1 sync/chunk.
//   Tile t: mtile = t>>2, nq = t&3; CTA bx owns t = bx, bx+296, ...
// ---------------------------------------------------------------------------
#define STAGE 32768
#define SMEM_DYN (3*STAGE)   // 96KB

__global__ __launch_bounds__(256, 2) void score_kernel(const float* __restrict__ Vw) {
    extern __shared__ char dsm[];
    __shared__ float dp_s[128];
    __shared__ float vw_s[128];
    __shared__ float s_red[2][128];

    const uint32_t sb = smem_u32(dsm);
    const int bx   = blockIdx.x;
    const int tid  = threadIdx.x;
    const int wid  = tid >> 5;
    const int lane = tid & 31;
    const int m0 = (wid >> 1) * 32;       // warp m-offset (0..96)
    const int n0 = (wid & 1) * 64;        // warp n-offset (0/64)
    const int rl = lane >> 2;             // fragment row group 0..7
    const int qt = lane & 3;              // fragment col group

    // ldmatrix lane addressing constants (validated rounds 4-14)
    const int sub = lane >> 3, i8 = lane & 7;
    const uint32_t x8   = (uint32_t)i8;
    const uint32_t aRow = (uint32_t)(m0 + ((sub & 1) << 3) + i8) * 128;
    const uint32_t aCS  = (uint32_t)(sub >> 1);
    const uint32_t bRow = (uint32_t)(n0 + ((sub >> 1) << 3) + i8) * 128;
    const uint32_t bCS  = (uint32_t)(sub & 1);

    uint32_t aChunk[4], bChunk[4];
    #pragma unroll
    for (int ks = 0; ks < 4; ks++) {
        aChunk[ks] = (((uint32_t)(2*ks) + aCS) ^ x8) << 4;
        bChunk[ks] = (((uint32_t)(2*ks) + bCS) ^ x8) << 4;
    }

    const int ntiles = (TILES - 1 - bx) / SGRID + 1;
    const int total  = ntiles * 8;        // chunks for this CTA

    float acc[2][8][4];
    #pragma unroll
    for (int mi = 0; mi < 2; mi++)
        #pragma unroll
        for (int j = 0; j < 8; j++)
            #pragma unroll
            for (int c = 0; c < 4; c++) acc[mi][j][c] = 0.f;

    // ---- producer: global chunk c -> tile (c>>3), k-chunk (c&7) ----
    auto produce = [&](int c) {
        const int t = bx + (c >> 3) * SGRID;
        const int kk = (c & 7) * 64;
        const __half* Ap = g_enc16 + (size_t)((t >> 2) * 128) * DD;
        const __half* Wp = g_W1T + (size_t)((t & 3) * 128) * DD;
        const uint32_t as = sb + (uint32_t)(c % 3) * STAGE;
        const uint32_t ws = as + 16384;
        #pragma unroll
        for (int i = 0; i < 4; i++) {          // A: 1024 x 16B
            int id = tid + i*256;
            int r = id >> 3, j = id & 7;
            uint32_t off = (uint32_t)r*128 + (uint32_t)((j ^ (r & 7)) << 4);
            cp16(as + off, Ap + (size_t)r*DD + kk + j*8);
        }
        #pragma unroll
        for (int i = 0; i < 4; i++) {          // W: 1024 x 16B
            int id = tid + i*256;
            int r = id >> 3, j = id & 7;
            uint32_t off = (uint32_t)r*128 + (uint32_t)((j ^ (r & 7)) << 4);
            cp16(ws + off, Wp + (size_t)r*DD + kk + j*8);
        }
        cp_commit();
    };

    // ---- prologue: fill 2 of 3 stages (paid ONCE per CTA) ----
    produce(0);
    produce(1);

    // ---- persistent mainloop over all chunks ----
    #pragma unroll 1
    for (int c = 0; c < total; c++) {
        if (c < total - 1) { CP_WAIT(1); } else { CP_WAIT(0); }
        __syncthreads();                   // chunk c ready; stage c-1 drained
        if (c + 2 < total) produce(c + 2); // overwrites stage consumed at c-1

        const int t = bx + (c >> 3) * SGRID;
        const int kt = c & 7;
        const int mtile = t >> 2, nq = t & 3;

        if (kt == 0 && tid < 128) {        // per-tile epilogue vectors
            dp_s[tid] = g_dec_proj[(mtile / 6)*UU + nq*128 + tid];
            vw_s[tid] = Vw[nq*128 + tid];
        }

        const uint32_t st  = sb + (uint32_t)(c % 3) * STAGE;
        const uint32_t stW = st + 16384u;
        #pragma unroll
        for (int ks = 0; ks < 4; ks++) {
            uint32_t bq[4][4];
            #pragma unroll
            for (int jp = 0; jp < 4; jp++)
                ldsm4(bq[jp], stW + bRow + (uint32_t)jp*2048 + bChunk[ks]);
            uint32_t a0[4], a1[4];
            ldsm4(a0, st + aRow + aChunk[ks]);
            ldsm4(a1, st + aRow + 2048 + aChunk[ks]);
            #pragma unroll
            for (int jp = 0; jp < 4; jp++) {
                mma_f16(acc[0][2*jp],   a0, bq[jp][0], bq[jp][1]);
                mma_f16(acc[1][2*jp],   a1, bq[jp][0], bq[jp][1]);
                mma_f16(acc[0][2*jp+1], a0, bq[jp][2], bq[jp][3]);
                mma_f16(acc[1][2*jp+1], a1, bq[jp][2], bq[jp][3]);
            }
        }

        if (kt == 7) {
            // ---- epilogue: fast tanh + V-dot (overlaps next tile's loads) ----
            float p[4] = {0.f, 0.f, 0.f, 0.f};
            #pragma unroll
            for (int mi = 0; mi < 2; mi++)
                #pragma unroll
                for (int j = 0; j < 8; j++)
                    #pragma unroll
                    for (int cc = 0; cc < 4; cc++) {
                        int u = n0 + j*8 + qt*2 + (cc & 1);
                        int h = cc >> 1;
                        p[mi*2 + h] += fast_tanh(acc[mi][j][cc] + dp_s[u]) * vw_s[u];
                    }
            #pragma unroll
            for (int i = 0; i < 4; i++) {
                p[i] += __shfl_xor_sync(0xFFFFFFFF, p[i], 1);
                p[i] += __shfl_xor_sync(0xFFFFFFFF, p[i], 2);
            }
            if (qt == 0) {
                #pragma unroll
                for (int mi = 0; mi < 2; mi++)
                    #pragma unroll
                    for (int h = 0; h < 2; h++)
                        s_red[wid & 1][m0 + mi*16 + h*8 + rl] = p[mi*2 + h];
            }
            __syncthreads();
            if (tid < 128)
                g_part[nq*MM + mtile*128 + tid] = s_red[0][tid] + s_red[1][tid];
            // reset accumulators for next tile
            #pragma unroll
            for (int mi = 0; mi < 2; mi++)
                #pragma unroll
                for (int j = 0; j < 8; j++)
                    #pragma unroll
                    for (int cc = 0; cc < 4; cc++) acc[mi][j][cc] = 0.f;
        }
    }
}

// ---------------------------------------------------------------------------
// K4: fused softmax + context (atomic accumulate). grid(128,8), 128 threads.
//   Block (b,q): recomputes softmax over H for batch b (from g_part, L2-hot),
//   writes attn rows h=2q,2q+1 (exactly once across q), then atomically adds
//   its 96-row context partial into ctx_out (zeroed by prep_all).
// ---------------------------------------------------------------------------
__global__ __launch_bounds__(128) void ctx_sm_kernel(float* __restrict__ attn,
                                                     float* __restrict__ ctx_out) {
    __shared__ float sc[HW];
    __shared__ float s_a[96];
    int b = blockIdx.x, q = blockIdx.y;
    int t = threadIdx.x;
    int base = q * 96;

    // load + sum 4 score planes for the whole batch
    #pragma unroll
    for (int i = t; i < HW; i += 128) {
        const float* p0 = g_part + b*HW + i;
        sc[i] = (p0[0] + p0[MM]) + (p0[2*MM] + p0[3*MM]);
    }
    __syncthreads();

    // softmax over h per w; write attn rows h0=2q, h0+1
    if (t < WW) {
        int w = t;
        int h0 = 2*q;
        float mx = -1e30f;
        #pragma unroll
        for (int h = 0; h < HH; h++) mx = fmaxf(mx, sc[h*WW + w]);
        float sum = 0.f, e0 = 0.f, e1 = 0.f;
        #pragma unroll
        for (int h = 0; h < HH; h++) {
            float e = __expf(sc[h*WW + w] - mx);
            sum += e;
            if (h == h0)     e0 = e;
            if (h == h0 + 1) e1 = e;
        }
        float inv = 1.0f / sum;
        float a0 = e0 * inv, a1 = e1 * inv;
        attn[b*HW + h0*WW + w] = a0;
        attn[b*HW + (h0+1)*WW + w] = a1;
        s_a[w] = a0;
        s_a[WW + w] = a1;
    }
    __syncthreads();

    // context partial over 96 rows
    const uint2* __restrict__ e =
        (const uint2*)(g_enc16 + ((size_t)b*HW + base)*DD) + t;   // 4 halves/thread
    float4 a0 = {0,0,0,0}, a1 = a0, a2 = a0, a3 = a0;
    #pragma unroll 4
    for (int i = 0; i < 96; i += 4) {
        float w0 = s_a[i], w1 = s_a[i+1], w2 = s_a[i+2], w3 = s_a[i+3];
        uint2 v0 = e[(size_t)(i+0)*128];
        uint2 v1 = e[(size_t)(i+1)*128];
        uint2 v2 = e[(size_t)(i+2)*128];
        uint2 v3 = e[(size_t)(i+3)*128];
        float2 f0a = __half22float2(reinterpret_cast<__half2&>(v0.x));
        float2 f0b = __half22float2(reinterpret_cast<__half2&>(v0.y));
        float2 f1a = __half22float2(reinterpret_cast<__half2&>(v1.x));
        float2 f1b = __half22float2(reinterpret_cast<__half2&>(v1.y));
        float2 f2a = __half22float2(reinterpret_cast<__half2&>(v2.x));
        float2 f2b = __half22float2(reinterpret_cast<__half2&>(v2.y));
        float2 f3a = __half22float2(reinterpret_cast<__half2&>(v3.x));
        float2 f3b = __half22float2(reinterpret_cast<__half2&>(v3.y));
        a0.x += w0*f0a.x; a0.y += w0*f0a.y; a0.z += w0*f0b.x; a0.w += w0*f0b.y;
        a1.x += w1*f1a.x; a1.y += w1*f1a.y; a1.z += w1*f1b.x; a1.w += w1*f1b.y;
        a2.x += w2*f2a.x; a2.y += w2*f2a.y; a2.z += w2*f2b.x; a2.w += w2*f2b.y;
        a3.x += w3*f3a.x; a3.y += w3*f3a.y; a3.z += w3*f3b.x; a3.w += w3*f3b.y;
    }
    float* dst = ctx_out + (size_t)b*DD + t*4;
    atomicAdd(dst + 0, (a0.x + a1.x) + (a2.x + a3.x));
    atomicAdd(dst + 1, (a0.y + a1.y) + (a2.y + a3.y));
    atomicAdd(dst + 2, (a0.z + a1.z) + (a2.z + a3.z));
    atomicAdd(dst + 3, (a0.w + a1.w) + (a2.w + a3.w));
}

// ---------------------------------------------------------------------------
extern "C" void kernel_launch(void* const* d_in, const int* in_sizes, int n_in,
                              void* d_out, int out_size) {
    const float* dec  = (const float*)d_in[0];   // (128, 512)
    const float* enc  = (const float*)d_in[1];   // (128, 16, 48, 512)
    const float* W1w  = (const float*)d_in[2];   // (512, 512)
    const float* W1b  = (const float*)d_in[3];
    const float* W2w  = (const float*)d_in[4];
    const float* W2b  = (const float*)d_in[5];
    const float* Vw   = (const float*)d_in[6];   // (512, 1)
    // V_b unused: cancels in softmax.

    float* ctx_out  = (float*)d_out;             // (128, 512)
    float* attn_out = (float*)d_out + BB*DD;     // (128, 16, 48, 1)

    static bool attr_set = false;
    if (!attr_set) {
        cudaFuncSetAttribute(score_kernel,
                             cudaFuncAttributeMaxDynamicSharedMemorySize, SMEM_DYN);
        attr_set = true;
    }

    prep_all_kernel<<<Z_BLKS + DP_BLKS + W1_BLKS + ENC_BLKS, 256>>>(
        enc, W1w, dec, W2w, W1b, W2b, ctx_out);
    score_kernel<<<SGRID, 256, SMEM_DYN>>>(Vw);
    ctx_sm_kernel<<<dim3(BB, 8), 128>>>(attn_out, ctx_out);
}

// round 16
// speedup vs baseline: 1.1863x; 1.1645x over previous
#include <cuda_runtime.h>
#include <cuda_fp16.h>
#include <cstdint>
#include <math.h>

// Problem constants
#define BB 128
#define HH 16
#define WW 48
#define DD 512
#define UU 512
#define HW (HH*WW)          // 768
#define MM (BB*HW)          // 98304

// ---------------------------------------------------------------------------
// Device globals (scratch; no allocation allowed)
// ---------------------------------------------------------------------------
__device__ float  g_dec_proj[BB*UU];          // dec @ W2 + b1 + b2
__device__ float  g_part[4*MM];               // partial scores per N-quarter
__device__ __half g_W1T[UU*DD];               // W1^T fp16 [u][k]
__device__ __half g_enc16[(size_t)MM*DD];     // enc fp16 [m][k]

// ---------------------------------------------------------------------------
// Helpers
// ---------------------------------------------------------------------------
__device__ __forceinline__ uint32_t smem_u32(const void* p) {
    uint32_t a;
    asm("{ .reg .u64 t; cvta.to.shared.u64 t, %1; cvt.u32.u64 %0, t; }"
        : "=r"(a) : "l"(p));
    return a;
}

__device__ __forceinline__ void cp16(uint32_t s, const void* g) {
    asm volatile("cp.async.cg.shared.global [%0], [%1], 16;"
                 :: "r"(s), "l"(g) : "memory");
}
__device__ __forceinline__ void cp_commit() {
    asm volatile("cp.async.commit_group;" ::: "memory");
}
#define CP_WAIT(n) asm volatile("cp.async.wait_group %0;" :: "n"(n) : "memory")

__device__ __forceinline__ void ldsm4(uint32_t* r, uint32_t addr) {
    asm volatile("ldmatrix.sync.aligned.m8n8.x4.shared.b16 {%0,%1,%2,%3}, [%4];"
                 : "=r"(r[0]), "=r"(r[1]), "=r"(r[2]), "=r"(r[3]) : "r"(addr));
}

__device__ __forceinline__ void mma_f16(float* c, const uint32_t* a,
                                        uint32_t b0, uint32_t b1) {
    asm volatile("mma.sync.aligned.m16n8k16.row.col.f32.f16.f16.f32 "
                 "{%0,%1,%2,%3}, {%4,%5,%6,%7}, {%8,%9}, {%0,%1,%2,%3};"
                 : "+f"(c[0]), "+f"(c[1]), "+f"(c[2]), "+f"(c[3])
                 : "r"(a[0]), "r"(a[1]), "r"(a[2]), "r"(a[3]),
                   "r"(b0), "r"(b1));
}

// fast tanh: (e^{2x}-1)/(e^{2x}+1), clamped so e^{2x} never overflows
__device__ __forceinline__ float fast_tanh(float x) {
    x = fminf(10.f, fmaxf(-10.f, x));
    float t = __expf(2.f * x);
    return __fdividef(t - 1.f, t + 1.f);
}

// ---------------------------------------------------------------------------
// K0: merged prep, 512-thread blocks (half the block count of R13).
//   Blocks [0, 16):            zero d_out ctx region (2 float4s/thread)
//   Blocks [16, 144):          dec_proj, 1 batch per block (u = tid)
//   Blocks [144, 272):         W1 -> transposed fp16 (512 float4s each)
//   Blocks [272, 272+24576):   enc fp32 -> fp16 (1 float4 per thread)
// ---------------------------------------------------------------------------
#define Z_BLKS    16
#define DP_BLKS   128
#define W1_BLKS   128
#define ENC_BLKS  24576      // MM*DD/4 float4s / 512 threads

__global__ __launch_bounds__(512) void prep_all_kernel(
    const float* __restrict__ enc, const float* __restrict__ W1,
    const float* __restrict__ dec, const float* __restrict__ W2,
    const float* __restrict__ b1, const float* __restrict__ b2,
    float* __restrict__ ctx_out) {
    const int bx = blockIdx.x;
    const int tid = threadIdx.x;

    if (bx >= Z_BLKS + DP_BLKS + W1_BLKS) {
        // enc fp32 -> fp16  (streaming loads: fp32 never reused)
        size_t i4 = (size_t)(bx - Z_BLKS - DP_BLKS - W1_BLKS) * 512 + tid;
        float4 v = __ldcs((const float4*)enc + i4);
        __half2 h01 = __floats2half2_rn(v.x, v.y);
        __half2 h23 = __floats2half2_rn(v.z, v.w);
        ((uint2*)g_enc16)[i4] = make_uint2(reinterpret_cast<uint32_t&>(h01),
                                           reinterpret_cast<uint32_t&>(h23));
    } else if (bx >= Z_BLKS + DP_BLKS) {
        // W1[k][u] -> g_W1T[u][k] fp16  (512 float4s per block)
        int i4 = (bx - Z_BLKS - DP_BLKS) * 512 + tid;  // 0..65535
        int base = i4 * 4;
        int k = base >> 9, u = base & 511;
        float4 v = *(const float4*)(W1 + base);
        g_W1T[(u+0)*DD + k] = __float2half_rn(v.x);
        g_W1T[(u+1)*DD + k] = __float2half_rn(v.y);
        g_W1T[(u+2)*DD + k] = __float2half_rn(v.z);
        g_W1T[(u+3)*DD + k] = __float2half_rn(v.w);
    } else if (bx >= Z_BLKS) {
        // dec_proj: one batch per block; thread owns u = tid (512 threads)
        __shared__ float s_dec[DD];
        int b0 = bx - Z_BLKS;
        s_dec[tid] = dec[b0*DD + tid];
        __syncthreads();
        float a0 = b1[tid] + b2[tid];
        #pragma unroll 8
        for (int d = 0; d < DD; d++)
            a0 += s_dec[d] * W2[(size_t)d*UU + tid];
        g_dec_proj[b0*UU + tid] = a0;
    } else {
        // zero the ctx region of d_out (atomic accumulation target)
        int i = bx * 512 + tid;            // 0..8191, 2 float4s each
        float4 z = {0.f, 0.f, 0.f, 0.f};
        ((float4*)ctx_out)[i] = z;
        ((float4*)ctx_out)[i + 8192] = z;
    }
}

// ---------------------------------------------------------------------------
// K2: fp16 score GEMM (R13 validated), 2 CTAs/SM.  CTA tile 128x128,
//   256 threads, 8 warps (4m x 2n, warp tile 32x64). K-chunk 64.
//   Stage = A 16K + W 16K = 32KB; 3 stages = 96KB; 1 sync/chunk.
//   grid = 3072: mtile = bx>>2, nq = bx&3 (n-fast for A L2 reuse).
// ---------------------------------------------------------------------------
#define STAGE 32768
#define SMEM_DYN (3*STAGE)   // 96KB

__global__ __launch_bounds__(256, 2) void score_kernel(const float* __restrict__ Vw) {
    extern __shared__ char dsm[];
    __shared__ float dp_s[128];
    __shared__ float vw_s[128];
    __shared__ float s_red[2][128];

    const uint32_t sb = smem_u32(dsm);
    const int tid  = threadIdx.x;
    const int wid  = tid >> 5;
    const int lane = tid & 31;
    const int mtile = blockIdx.x >> 2;
    const int nq    = blockIdx.x & 3;
    const int row0  = mtile * 128;
    const int b     = mtile / 6;          // 6 m-tiles per batch
    const int m0 = (wid >> 1) * 32;       // warp m-offset (0..96)
    const int n0 = (wid & 1) * 64;        // warp n-offset (0/64)
    const int rl = lane >> 2;             // fragment row group 0..7
    const int qt = lane & 3;              // fragment col group

    // ldmatrix lane addressing constants (validated rounds 4-15)
    const int sub = lane >> 3, i8 = lane & 7;
    const uint32_t x8   = (uint32_t)i8;
    const uint32_t aRow = (uint32_t)(m0 + ((sub & 1) << 3) + i8) * 128;
    const uint32_t aCS  = (uint32_t)(sub >> 1);
    const uint32_t bRow = (uint32_t)(n0 + ((sub >> 1) << 3) + i8) * 128;
    const uint32_t bCS  = (uint32_t)(sub & 1);

    uint32_t aChunk[4], bChunk[4];
    #pragma unroll
    for (int ks = 0; ks < 4; ks++) {
        aChunk[ks] = (((uint32_t)(2*ks) + aCS) ^ x8) << 4;
        bChunk[ks] = (((uint32_t)(2*ks) + bCS) ^ x8) << 4;
    }

    if (tid < 128) {
        dp_s[tid] = g_dec_proj[b*UU + nq*128 + tid];
        vw_s[tid] = Vw[nq*128 + tid];
    }

    float acc[2][8][4];
    #pragma unroll
    for (int mi = 0; mi < 2; mi++)
        #pragma unroll
        for (int j = 0; j < 8; j++)
            #pragma unroll
            for (int c = 0; c < 4; c++) acc[mi][j][c] = 0.f;

    const __half* __restrict__ Ap = g_enc16 + (size_t)row0*DD;
    const __half* __restrict__ Wp = g_W1T + (size_t)(nq*128)*DD;

    // ---- producer: one K=64 chunk (A + W), all cp.async ----
    auto produce = [&](int kt) {
        const uint32_t as = sb + (uint32_t)(kt % 3)*STAGE;
        const uint32_t ws = as + 16384;
        const int kk = kt * 64;
        #pragma unroll
        for (int i = 0; i < 4; i++) {          // A: 1024 x 16B
            int id = tid + i*256;
            int r = id >> 3, j = id & 7;
            uint32_t off = (uint32_t)r*128 + (uint32_t)((j ^ (r & 7)) << 4);
            cp16(as + off, Ap + (size_t)r*DD + kk + j*8);
        }
        #pragma unroll
        for (int i = 0; i < 4; i++) {          // W: 1024 x 16B
            int id = tid + i*256;
            int r = id >> 3, j = id & 7;
            uint32_t off = (uint32_t)r*128 + (uint32_t)((j ^ (r & 7)) << 4);
            cp16(ws + off, Wp + (size_t)r*DD + kk + j*8);
        }
        cp_commit();
    };

    // ---- prologue: fill 2 of 3 stages ----
    produce(0);
    produce(1);

    // ---- mainloop: 8 chunks, ONE sync per chunk ----
    #pragma unroll 1
    for (int kt = 0; kt < 8; kt++) {
        if (kt < 7) { CP_WAIT(1); } else { CP_WAIT(0); }
        __syncthreads();                   // chunk kt ready; stage kt-1 drained
        if (kt + 2 < 8) produce(kt + 2);   // overwrites stage consumed at kt-1

        const uint32_t st  = sb + (uint32_t)(kt % 3)*STAGE;
        const uint32_t stW = st + 16384u;
        #pragma unroll
        for (int ks = 0; ks < 4; ks++) {
            uint32_t bq[4][4];
            #pragma unroll
            for (int jp = 0; jp < 4; jp++)
                ldsm4(bq[jp], stW + bRow + (uint32_t)jp*2048 + bChunk[ks]);
            uint32_t a0[4], a1[4];
            ldsm4(a0, st + aRow + aChunk[ks]);
            ldsm4(a1, st + aRow + 2048 + aChunk[ks]);
            #pragma unroll
            for (int jp = 0; jp < 4; jp++) {
                mma_f16(acc[0][2*jp],   a0, bq[jp][0], bq[jp][1]);
                mma_f16(acc[1][2*jp],   a1, bq[jp][0], bq[jp][1]);
                mma_f16(acc[0][2*jp+1], a0, bq[jp][2], bq[jp][3]);
                mma_f16(acc[1][2*jp+1], a1, bq[jp][2], bq[jp][3]);
            }
        }
    }

    // ---- epilogue: fast tanh + V-dot ----
    float p[4] = {0.f, 0.f, 0.f, 0.f};
    #pragma unroll
    for (int mi = 0; mi < 2; mi++)
        #pragma unroll
        for (int j = 0; j < 8; j++)
            #pragma unroll
            for (int cc = 0; cc < 4; cc++) {
                int u = n0 + j*8 + qt*2 + (cc & 1);
                int h = cc >> 1;
                p[mi*2 + h] += fast_tanh(acc[mi][j][cc] + dp_s[u]) * vw_s[u];
            }
    #pragma unroll
    for (int i = 0; i < 4; i++) {
        p[i] += __shfl_xor_sync(0xFFFFFFFF, p[i], 1);
        p[i] += __shfl_xor_sync(0xFFFFFFFF, p[i], 2);
    }
    if (qt == 0) {
        #pragma unroll
        for (int mi = 0; mi < 2; mi++)
            #pragma unroll
            for (int h = 0; h < 2; h++)
                s_red[wid & 1][m0 + mi*16 + h*8 + rl] = p[mi*2 + h];
    }
    __syncthreads();
    if (tid < 128)
        g_part[nq*MM + row0 + tid] = s_red[0][tid] + s_red[1][tid];
}

// ---------------------------------------------------------------------------
// K4: fused softmax + context (atomic accumulate). grid(128,8), 128 threads.
// ---------------------------------------------------------------------------
__global__ __launch_bounds__(128) void ctx_sm_kernel(float* __restrict__ attn,
                                                     float* __restrict__ ctx_out) {
    __shared__ float sc[HW];
    __shared__ float s_a[96];
    int b = blockIdx.x, q = blockIdx.y;
    int t = threadIdx.x;
    int base = q * 96;

    // load + sum 4 score planes for the whole batch
    #pragma unroll
    for (int i = t; i < HW; i += 128) {
        const float* p0 = g_part + b*HW + i;
        sc[i] = (p0[0] + p0[MM]) + (p0[2*MM] + p0[3*MM]);
    }
    __syncthreads();

    // softmax over h per w; write attn rows h0=2q, h0+1
    if (t < WW) {
        int w = t;
        int h0 = 2*q;
        float mx = -1e30f;
        #pragma unroll
        for (int h = 0; h < HH; h++) mx = fmaxf(mx, sc[h*WW + w]);
        float sum = 0.f, e0 = 0.f, e1 = 0.f;
        #pragma unroll
        for (int h = 0; h < HH; h++) {
            float e = __expf(sc[h*WW + w] - mx);
            sum += e;
            if (h == h0)     e0 = e;
            if (h == h0 + 1) e1 = e;
        }
        float inv = 1.0f / sum;
        float a0 = e0 * inv, a1 = e1 * inv;
        attn[b*HW + h0*WW + w] = a0;
        attn[b*HW + (h0+1)*WW + w] = a1;
        s_a[w] = a0;
        s_a[WW + w] = a1;
    }
    __syncthreads();

    // context partial over 96 rows
    const uint2* __restrict__ e =
        (const uint2*)(g_enc16 + ((size_t)b*HW + base)*DD) + t;   // 4 halves/thread
    float4 a0 = {0,0,0,0}, a1 = a0, a2 = a0, a3 = a0;
    #pragma unroll 4
    for (int i = 0; i < 96; i += 4) {
        float w0 = s_a[i], w1 = s_a[i+1], w2 = s_a[i+2], w3 = s_a[i+3];
        uint2 v0 = e[(size_t)(i+0)*128];
        uint2 v1 = e[(size_t)(i+1)*128];
        uint2 v2 = e[(size_t)(i+2)*128];
        uint2 v3 = e[(size_t)(i+3)*128];
        float2 f0a = __half22float2(reinterpret_cast<__half2&>(v0.x));
        float2 f0b = __half22float2(reinterpret_cast<__half2&>(v0.y));
        float2 f1a = __half22float2(reinterpret_cast<__half2&>(v1.x));
        float2 f1b = __half22float2(reinterpret_cast<__half2&>(v1.y));
        float2 f2a = __half22float2(reinterpret_cast<__half2&>(v2.x));
        float2 f2b = __half22float2(reinterpret_cast<__half2&>(v2.y));
        float2 f3a = __half22float2(reinterpret_cast<__half2&>(v3.x));
        float2 f3b = __half22float2(reinterpret_cast<__half2&>(v3.y));
        a0.x += w0*f0a.x; a0.y += w0*f0a.y; a0.z += w0*f0b.x; a0.w += w0*f0b.y;
        a1.x += w1*f1a.x; a1.y += w1*f1a.y; a1.z += w1*f1b.x; a1.w += w1*f1b.y;
        a2.x += w2*f2a.x; a2.y += w2*f2a.y; a2.z += w2*f2b.x; a2.w += w2*f2b.y;
        a3.x += w3*f3a.x; a3.y += w3*f3a.y; a3.z += w3*f3b.x; a3.w += w3*f3b.y;
    }
    float* dst = ctx_out + (size_t)b*DD + t*4;
    atomicAdd(dst + 0, (a0.x + a1.x) + (a2.x + a3.x));
    atomicAdd(dst + 1, (a0.y + a1.y) + (a2.y + a3.y));
    atomicAdd(dst + 2, (a0.z + a1.z) + (a2.z + a3.z));
    atomicAdd(dst + 3, (a0.w + a1.w) + (a2.w + a3.w));
}

// ---------------------------------------------------------------------------
extern "C" void kernel_launch(void* const* d_in, const int* in_sizes, int n_in,
                              void* d_out, int out_size) {
    const float* dec  = (const float*)d_in[0];   // (128, 512)
    const float* enc  = (const float*)d_in[1];   // (128, 16, 48, 512)
    const float* W1w  = (const float*)d_in[2];   // (512, 512)
    const float* W1b  = (const float*)d_in[3];
    const float* W2w  = (const float*)d_in[4];
    const float* W2b  = (const float*)d_in[5];
    const float* Vw   = (const float*)d_in[6];   // (512, 1)
    // V_b unused: cancels in softmax.

    float* ctx_out  = (float*)d_out;             // (128, 512)
    float* attn_out = (float*)d_out + BB*DD;     // (128, 16, 48, 1)

    static bool attr_set = false;
    if (!attr_set) {
        cudaFuncSetAttribute(score_kernel,
                             cudaFuncAttributeMaxDynamicSharedMemorySize, SMEM_DYN);
        attr_set = true;
    }

    prep_all_kernel<<<Z_BLKS + DP_BLKS + W1_BLKS + ENC_BLKS, 512>>>(
        enc, W1w, dec, W2w, W1b, W2b, ctx_out);
    score_kernel<<<(MM/128)*4, 256, SMEM_DYN>>>(Vw);
    ctx_sm_kernel<<<dim3(BB, 8), 128>>>(attn_out, ctx_out);
}